// round 9
// baseline (speedup 1.0000x reference)
#include <cuda_runtime.h>

#define S_LEN 2048
#define BSZ   2
#define EMB   1024
#define NH    16
#define DH    64
#define MROWS 4096
#define NHEADS 32
#define S2 ((long)S_LEN*S_LEN)

// Scratch (__device__ globals per alloc-free rule)
__device__ float g_Qp[MROWS*EMB];   // column-pair-permuted, RNA tf32 bits
__device__ float g_Kp[MROWS*EMB];   // column-pair-permuted, RNA tf32 bits
__device__ float g_Vp[MROWS*EMB];   // normal layout, fp32
__device__ float g_O [MROWS*EMB];
__device__ float g_m [NHEADS*S_LEN];
__device__ float g_l [NHEADS*S_LEN];

__device__ __forceinline__ unsigned f2tf(float f){
    unsigned u; asm("cvt.rna.tf32.f32 %0, %1;" : "=r"(u) : "f"(f)); return u;
}
__device__ __forceinline__ void mma8(float* c, const unsigned* a, const unsigned* b){
    asm volatile("mma.sync.aligned.m16n8k8.row.col.f32.tf32.tf32.f32 "
      "{%0,%1,%2,%3}, {%4,%5,%6,%7}, {%8,%9}, {%0,%1,%2,%3};\n"
      : "+f"(c[0]), "+f"(c[1]), "+f"(c[2]), "+f"(c[3])
      : "r"(a[0]), "r"(a[1]), "r"(a[2]), "r"(a[3]), "r"(b[0]), "r"(b[1]));
}
__device__ __forceinline__ void cpa16(void* dst, const void* src){
    unsigned d = (unsigned)__cvta_generic_to_shared(dst);
    asm volatile("cp.async.cg.shared.global [%0], [%1], 16;\n" :: "r"(d), "l"(src));
}

// ---------------------------------------------------------------------------
// TN tf32 GEMM body v2: pair-permuted smem (stride 24) -> LDS.64 fragment
// loads, conflict-free. permOut: C written column-pair-permuted AND as RNA
// tf32 bits (for flash/avg consumers).
// Fixed shape: BM=64, BN=128, BK=16, WM=32, WN=32, 8 warps.
// ---------------------------------------------------------------------------
__device__ __forceinline__
void gemm_body(const float* __restrict__ A, int lda,
               const float* __restrict__ B, int ldb,
               float* __restrict__ C, int ldc,
               const float* __restrict__ bias, float scale, int K,
               int m0, int n0, bool permOut)
{
    constexpr int LDS_ = 24;
    __shared__ unsigned As[2][64][LDS_];
    __shared__ unsigned Bs[2][128][LDS_];

    const int tid  = threadIdx.x;
    const int lane = tid & 31, wid = tid >> 5;
    const int wm = wid >> 2, wn = wid & 3;      // 2 x 4 warp grid (WM=32, WN=32)

    float acc[2][4][4] = {};
    float4 ra0, ra1, rb0, rb1;
    const int rA = tid >> 1, hA = (tid & 1) * 8;     // valid for tid < 128
    const int rB = tid >> 1, hB = (tid & 1) * 8;

    auto ldtiles = [&](int k0){
        if (tid < 128){
            ra0 = *(const float4*)(A + (long)(m0+rA)*lda + k0 + hA);
            ra1 = *(const float4*)(A + (long)(m0+rA)*lda + k0 + hA + 4);
        }
        rb0 = *(const float4*)(B + (long)(n0+rB)*ldb + k0 + hB);
        rb1 = *(const float4*)(B + (long)(n0+rB)*ldb + k0 + hB + 4);
    };
    auto sttiles = [&](int buf){
        if (tid < 128){
            uint4 u0 = { f2tf(ra0.x), f2tf(ra1.x), f2tf(ra0.y), f2tf(ra1.y) };
            uint4 u1 = { f2tf(ra0.z), f2tf(ra1.z), f2tf(ra0.w), f2tf(ra1.w) };
            *(uint4*)&As[buf][rA][hA    ] = u0;
            *(uint4*)&As[buf][rA][hA + 4] = u1;
        }
        uint4 v0 = { f2tf(rb0.x), f2tf(rb1.x), f2tf(rb0.y), f2tf(rb1.y) };
        uint4 v1 = { f2tf(rb0.z), f2tf(rb1.z), f2tf(rb0.w), f2tf(rb1.w) };
        *(uint4*)&Bs[buf][rB][hB    ] = v0;
        *(uint4*)&Bs[buf][rB][hB + 4] = v1;
    };
    auto compute = [&](int buf){
        #pragma unroll
        for (int ks = 0; ks < 2; ++ks){
            const int col = ks*8 + 2*(lane&3);
            unsigned af[2][4], bf[4][2];
            #pragma unroll
            for (int mi = 0; mi < 2; ++mi){
                int m = wm*32 + mi*16 + (lane>>2);
                uint2 u0 = *(const uint2*)&As[buf][m  ][col];
                uint2 u1 = *(const uint2*)&As[buf][m+8][col];
                af[mi][0] = u0.x; af[mi][1] = u1.x; af[mi][2] = u0.y; af[mi][3] = u1.y;
            }
            #pragma unroll
            for (int ni = 0; ni < 4; ++ni){
                int n = wn*32 + ni*8 + (lane>>2);
                uint2 ub = *(const uint2*)&Bs[buf][n][col];
                bf[ni][0] = ub.x; bf[ni][1] = ub.y;
            }
            #pragma unroll
            for (int mi = 0; mi < 2; ++mi)
                #pragma unroll
                for (int ni = 0; ni < 4; ++ni)
                    mma8(acc[mi][ni], af[mi], bf[ni]);
        }
    };

    ldtiles(0); sttiles(0); __syncthreads();
    const int nk = K/16;
    for (int t = 1; t < nk; ++t){
        ldtiles(t*16);
        compute((t-1)&1);
        sttiles(t&1);
        __syncthreads();
    }
    compute((nk-1)&1);

    #pragma unroll
    for (int mi = 0; mi < 2; ++mi){
        #pragma unroll
        for (int ni = 0; ni < 4; ++ni){
            int m = m0 + wm*32 + mi*16 + (lane>>2);
            int n = n0 + wn*32 + ni*8 + 2*(lane&3);
            float v0 = acc[mi][ni][0], v1 = acc[mi][ni][1];
            float v2 = acc[mi][ni][2], v3 = acc[mi][ni][3];
            float b0 = bias[n], b1 = bias[n+1];
            v0 = (v0+b0)*scale; v1 = (v1+b1)*scale;
            v2 = (v2+b0)*scale; v3 = (v3+b1)*scale;
            if (permOut){
                int p0 = (n & ~7) | ((n&3)<<1) | ((n>>2)&1);   // perm(n); perm(n+1)=p0+2
                C[(long)m    *ldc + p0    ] = __uint_as_float(f2tf(v0));
                C[(long)m    *ldc + p0 + 2] = __uint_as_float(f2tf(v1));
                C[(long)(m+8)*ldc + p0    ] = __uint_as_float(f2tf(v2));
                C[(long)(m+8)*ldc + p0 + 2] = __uint_as_float(f2tf(v3));
            } else {
                *(float2*)(C + (long)m    *ldc + n) = make_float2(v0, v1);
                *(float2*)(C + (long)(m+8)*ldc + n) = make_float2(v2, v3);
            }
        }
    }
}

// Merged Q/K/V projections: grid (8, 64, 3). Q,K -> permuted tf32 bits.
__global__ __launch_bounds__(256)
void qkv_proj(const float* __restrict__ q, const float* __restrict__ k, const float* __restrict__ v,
              const float* __restrict__ qw, const float* __restrict__ qb,
              const float* __restrict__ kw, const float* __restrict__ kb,
              const float* __restrict__ vw, const float* __restrict__ vb,
              float* __restrict__ qp, float* __restrict__ kp, float* __restrict__ vp)
{
    const int z = blockIdx.z;
    const float* A  = (z==0)? q  : (z==1)? k  : v;
    const float* W  = (z==0)? qw : (z==1)? kw : vw;
    const float* bi = (z==0)? qb : (z==1)? kb : vb;
    float*       C  = (z==0)? qp : (z==1)? kp : vp;
    const float scale = (z==0)? 0.125f : 1.0f;
    gemm_body(A, EMB, W, EMB, C, EMB, bi, scale, EMB,
              blockIdx.y*64, blockIdx.x*128, z<2);
}

// Output projection: grid (8, 64)
__global__ __launch_bounds__(256)
void out_proj(const float* __restrict__ A, const float* __restrict__ W,
              const float* __restrict__ bi, float* __restrict__ C)
{
    gemm_body(A, EMB, W, EMB, C, EMB, bi, 1.0f, EMB,
              blockIdx.y*64, blockIdx.x*128, false);
}

// ---------------------------------------------------------------------------
// Flash attention: q-tile 128, 4 warps (MI=2), k-tiles 32 double-buffered.
// Q/K arrive as permuted tf32 bits -> fragment loads are plain LDS.64.
// ---------------------------------------------------------------------------
__global__ __launch_bounds__(128)
void flash_attn(const float* __restrict__ qp, const float* __restrict__ kp,
                const float* __restrict__ vp, float* __restrict__ op,
                float* __restrict__ gm, float* __restrict__ gl)
{
    __shared__ __align__(16) unsigned SU[9216];
    const int tid = threadIdx.x, lane = tid&31, w = tid>>5;
    const int hb = blockIdx.x, h = hb&15, b = hb>>4;
    const int q0 = blockIdx.y*128;
    const long base = (long)b*EMB + h*DH;
    const float* Qg = qp + base + (long)q0*(BSZ*EMB);
    const float* Kg = kp + base;
    const float* Vg = vp + base;

    // stage Q (already tf32 bits, permuted)
    for (int i = tid; i < 2048; i += 128){
        int r = i>>4, c = (i&15)*4;
        cpa16(&SU[r*72 + c], Qg + (long)r*(BSZ*EMB) + c);
    }
    asm volatile("cp.async.commit_group;\n");
    asm volatile("cp.async.wait_group 0;\n");
    __syncthreads();

    unsigned Qa[8][2][4];
    {
        const int p = lane>>2, col0 = 2*(lane&3);
        #pragma unroll
        for (int ks = 0; ks < 8; ++ks)
            #pragma unroll
            for (int mi = 0; mi < 2; ++mi){
                int m = w*32 + mi*16 + p;
                int col = ks*8 + col0;
                uint2 u0 = *(const uint2*)&SU[ m   *72 + col];
                uint2 u1 = *(const uint2*)&SU[(m+8)*72 + col];
                Qa[ks][mi][0] = u0.x; Qa[ks][mi][1] = u1.x;
                Qa[ks][mi][2] = u0.y; Qa[ks][mi][3] = u1.y;
            }
    }
    __syncthreads();

    unsigned* const Kb0 = SU;
    unsigned* const Kb1 = SU + 2304;
    unsigned* const Vb0 = SU + 4608;
    unsigned* const Vb1 = SU + 6912;

    auto load_kv = [&](int kt, int sel){
        unsigned* Kb = sel ? Kb1 : Kb0;
        unsigned* Vb = sel ? Vb1 : Vb0;
        const long r0 = (long)kt*32;
        #pragma unroll
        for (int j = 0; j < 4; ++j){
            int cch = tid + j*128;
            int r = cch>>4, cc = (cch&15)*4;
            cpa16(&Kb[r*72 + cc], Kg + (r0+r)*(BSZ*EMB) + cc);
            cpa16(&Vb[r*72 + cc], Vg + (r0+r)*(BSZ*EMB) + cc);
        }
    };

    float m_[2][2] = {{-1e30f,-1e30f},{-1e30f,-1e30f}};
    float l_[2][2] = {};
    float o[2][8][4] = {};

    const int srcA = (lane & ~3) | ((lane&3)>>1);
    const int srcB = srcA + 2;
    const bool osel = (lane & 1);

    load_kv(0, 0);
    asm volatile("cp.async.commit_group;\n");

    for (int t = 0; t < 64; ++t){
        if (t < 63){
            load_kv(t+1, (t+1)&1);
            asm volatile("cp.async.commit_group;\n");
            asm volatile("cp.async.wait_group 1;\n");
        } else {
            asm volatile("cp.async.wait_group 0;\n");
        }
        __syncthreads();

        unsigned* Kb = (t&1) ? Kb1 : Kb0;
        unsigned* Vb = (t&1) ? Vb1 : Vb0;

        // S = Q K^T  (K fragments via plain LDS.64, bits already tf32)
        float c_[2][4][4] = {};
        #pragma unroll
        for (int ks = 0; ks < 8; ++ks){
            unsigned bf[4][2];
            #pragma unroll
            for (int ni = 0; ni < 4; ++ni){
                int n = ni*8 + (lane>>2);
                int col = ks*8 + 2*(lane&3);
                uint2 u = *(const uint2*)&Kb[n*72 + col];
                bf[ni][0] = u.x; bf[ni][1] = u.y;
            }
            #pragma unroll
            for (int mi = 0; mi < 2; ++mi)
                #pragma unroll
                for (int ni = 0; ni < 4; ++ni)
                    mma8(c_[mi][ni], Qa[ks][mi], bf[ni]);
        }

        // online softmax with rescale-skip
        #pragma unroll
        for (int mi = 0; mi < 2; ++mi){
            float mx0 = -1e30f, mx1 = -1e30f;
            #pragma unroll
            for (int ni = 0; ni < 4; ++ni){
                mx0 = fmaxf(mx0, fmaxf(c_[mi][ni][0], c_[mi][ni][1]));
                mx1 = fmaxf(mx1, fmaxf(c_[mi][ni][2], c_[mi][ni][3]));
            }
            mx0 = fmaxf(mx0, __shfl_xor_sync(0xffffffffu, mx0, 1));
            mx0 = fmaxf(mx0, __shfl_xor_sync(0xffffffffu, mx0, 2));
            mx1 = fmaxf(mx1, __shfl_xor_sync(0xffffffffu, mx1, 1));
            mx1 = fmaxf(mx1, __shfl_xor_sync(0xffffffffu, mx1, 2));
            float mn0 = fmaxf(m_[mi][0], mx0), mn1 = fmaxf(m_[mi][1], mx1);
            if (!__all_sync(0xffffffffu, (mn0 == m_[mi][0]) & (mn1 == m_[mi][1]))){
                float f0 = __expf(m_[mi][0] - mn0), f1 = __expf(m_[mi][1] - mn1);
                l_[mi][0] *= f0; l_[mi][1] *= f1;
                #pragma unroll
                for (int ni = 0; ni < 8; ++ni){
                    o[mi][ni][0]*=f0; o[mi][ni][1]*=f0;
                    o[mi][ni][2]*=f1; o[mi][ni][3]*=f1;
                }
                m_[mi][0] = mn0; m_[mi][1] = mn1;
            }
            float s0 = 0.f, s1 = 0.f;
            #pragma unroll
            for (int ni = 0; ni < 4; ++ni){
                c_[mi][ni][0] = __expf(c_[mi][ni][0]-m_[mi][0]);
                c_[mi][ni][1] = __expf(c_[mi][ni][1]-m_[mi][0]);
                c_[mi][ni][2] = __expf(c_[mi][ni][2]-m_[mi][1]);
                c_[mi][ni][3] = __expf(c_[mi][ni][3]-m_[mi][1]);
                s0 += c_[mi][ni][0]+c_[mi][ni][1];
                s1 += c_[mi][ni][2]+c_[mi][ni][3];
            }
            s0 += __shfl_xor_sync(0xffffffffu, s0, 1);
            s0 += __shfl_xor_sync(0xffffffffu, s0, 2);
            s1 += __shfl_xor_sync(0xffffffffu, s1, 1);
            s1 += __shfl_xor_sync(0xffffffffu, s1, 2);
            l_[mi][0] += s0; l_[mi][1] += s1;
        }

        // P @ V
        #pragma unroll
        for (int ks2 = 0; ks2 < 4; ++ks2){
            unsigned a[2][4];
            #pragma unroll
            for (int mi = 0; mi < 2; ++mi){
                float v00 = __shfl_sync(0xffffffffu, c_[mi][ks2][0], srcA);
                float v01 = __shfl_sync(0xffffffffu, c_[mi][ks2][1], srcA);
                float v10 = __shfl_sync(0xffffffffu, c_[mi][ks2][2], srcA);
                float v11 = __shfl_sync(0xffffffffu, c_[mi][ks2][3], srcA);
                float v40 = __shfl_sync(0xffffffffu, c_[mi][ks2][0], srcB);
                float v41 = __shfl_sync(0xffffffffu, c_[mi][ks2][1], srcB);
                float v50 = __shfl_sync(0xffffffffu, c_[mi][ks2][2], srcB);
                float v51 = __shfl_sync(0xffffffffu, c_[mi][ks2][3], srcB);
                a[mi][0] = f2tf(osel ? v01 : v00);
                a[mi][1] = f2tf(osel ? v11 : v10);
                a[mi][2] = f2tf(osel ? v41 : v40);
                a[mi][3] = f2tf(osel ? v51 : v50);
            }
            #pragma unroll
            for (int ni = 0; ni < 8; ++ni){
                int kk = ks2*8 + (lane&3);
                int n  = ni*8 + (lane>>2);
                unsigned bf[2] = { Vb[kk*72 + n], Vb[(kk+4)*72 + n] };
                mma8(o[0][ni], a[0], bf);
                mma8(o[1][ni], a[1], bf);
            }
        }
        __syncthreads();
    }

    float* Og = op + base + (long)q0*(BSZ*EMB);
    #pragma unroll
    for (int mi = 0; mi < 2; ++mi){
        float inv0 = 1.f/l_[mi][0], inv1 = 1.f/l_[mi][1];
        int m = w*32 + mi*16 + (lane>>2);
        #pragma unroll
        for (int ni = 0; ni < 8; ++ni){
            int d = ni*8 + 2*(lane&3);
            *(float2*)(Og + (long)m    *(BSZ*EMB) + d) = make_float2(o[mi][ni][0]*inv0, o[mi][ni][1]*inv0);
            *(float2*)(Og + (long)(m+8)*(BSZ*EMB) + d) = make_float2(o[mi][ni][2]*inv1, o[mi][ni][3]*inv1);
        }
        if ((lane & 3) == 0){
            gm[(long)hb*S_LEN + q0 + m]     = m_[mi][0];
            gm[(long)hb*S_LEN + q0 + m + 8] = m_[mi][1];
            gl[(long)hb*S_LEN + q0 + m]     = l_[mi][0];
            gl[(long)hb*S_LEN + q0 + m + 8] = l_[mi][1];
        }
    }
}

// ---------------------------------------------------------------------------
// attn_avg: 256 thr, k-tile 64, q-tile 128, double-buffered heads.
// Q/K tf32 bits -> fragment loads are plain LDS.64 (no cvt in loop).
// ---------------------------------------------------------------------------
__global__ __launch_bounds__(256)
void avg_attn(const float* __restrict__ qp, const float* __restrict__ kp,
              const float* __restrict__ gm, const float* __restrict__ gl,
              float* __restrict__ avg)
{
    extern __shared__ __align__(16) unsigned ASH[];
    constexpr int BUF = 128*72 + 64*72;
    const int tid = threadIdx.x, lane = tid&31, wid = tid>>5;
    const int k0 = blockIdx.x*64, q0 = blockIdx.y*128, b = blockIdx.z;
    const int rloc = wid*16 + (lane>>2);

    auto stage = [&](int h, int sel){
        unsigned* Qs = ASH + sel*BUF;
        unsigned* Ks = Qs + 128*72;
        const long base = (long)b*EMB + h*DH;
        #pragma unroll
        for (int j = 0; j < 8; ++j){
            int idx = tid + j*256;
            int r = idx>>4, c = (idx&15)*4;
            cpa16(&Qs[r*72 + c], qp + base + (long)(q0+r)*(BSZ*EMB) + c);
        }
        #pragma unroll
        for (int j = 0; j < 4; ++j){
            int idx = tid + j*256;
            int r = idx>>4, c = (idx&15)*4;
            cpa16(&Ks[r*72 + c], kp + base + (long)(k0+r)*(BSZ*EMB) + c);
        }
        asm volatile("cp.async.commit_group;\n");
    };

    float acc[8][4] = {};

    stage(0, 0);
    for (int h = 0; h < NH; ++h){
        if (h < NH-1){
            stage(h+1, (h+1)&1);
            asm volatile("cp.async.wait_group 1;\n");
        } else {
            asm volatile("cp.async.wait_group 0;\n");
        }
        __syncthreads();

        unsigned* Qs = ASH + (h&1)*BUF;
        unsigned* Ks = Qs + 128*72;

        float c_[8][4] = {};
        #pragma unroll
        for (int ks = 0; ks < 8; ++ks){
            int col = ks*8 + 2*(lane&3);
            uint2 u0 = *(const uint2*)&Qs[ rloc   *72 + col];
            uint2 u1 = *(const uint2*)&Qs[(rloc+8)*72 + col];
            unsigned a[4] = { u0.x, u1.x, u0.y, u1.y };
            #pragma unroll
            for (int ni = 0; ni < 8; ++ni){
                int n = ni*8 + (lane>>2);
                uint2 ub = *(const uint2*)&Ks[n*72 + col];
                unsigned bf[2] = { ub.x, ub.y };
                mma8(c_[ni], a, bf);
            }
        }

        const int hb = b*NH + h;
        float mm0 = gm[(long)hb*S_LEN + q0 + rloc];
        float mm1 = gm[(long)hb*S_LEN + q0 + rloc + 8];
        float il0 = 1.f / gl[(long)hb*S_LEN + q0 + rloc];
        float il1 = 1.f / gl[(long)hb*S_LEN + q0 + rloc + 8];
        #pragma unroll
        for (int ni = 0; ni < 8; ++ni){
            acc[ni][0] += __expf(c_[ni][0]-mm0)*il0;
            acc[ni][1] += __expf(c_[ni][1]-mm0)*il0;
            acc[ni][2] += __expf(c_[ni][2]-mm1)*il1;
            acc[ni][3] += __expf(c_[ni][3]-mm1)*il1;
        }
        __syncthreads();
    }

    float* out = avg + (long)b*S2;
    const float s = 1.0f/NH;
    #pragma unroll
    for (int ni = 0; ni < 8; ++ni){
        int kc = k0 + ni*8 + 2*(lane&3);
        *(float2*)(out + (long)(q0+rloc)  *S_LEN + kc) = make_float2(acc[ni][0]*s, acc[ni][1]*s);
        *(float2*)(out + (long)(q0+rloc+8)*S_LEN + kc) = make_float2(acc[ni][2]*s, acc[ni][3]*s);
    }
}

// ---------------------------------------------------------------------------
extern "C" void kernel_launch(void* const* d_in, const int* in_sizes, int n_in,
                              void* d_out, int out_size)
{
    const float* query = (const float*)d_in[0];
    const float* key   = (const float*)d_in[1];
    const float* value = (const float*)d_in[2];
    const float* q_w = (const float*)d_in[3];
    const float* q_b = (const float*)d_in[4];
    const float* k_w = (const float*)d_in[5];
    const float* k_b = (const float*)d_in[6];
    const float* v_w = (const float*)d_in[7];
    const float* v_b = (const float*)d_in[8];
    const float* out_w = (const float*)d_in[9];
    const float* out_b = (const float*)d_in[10];

    float *qp, *kp, *vp, *op, *gm, *gl;
    cudaGetSymbolAddress((void**)&qp, g_Qp);
    cudaGetSymbolAddress((void**)&kp, g_Kp);
    cudaGetSymbolAddress((void**)&vp, g_Vp);
    cudaGetSymbolAddress((void**)&op, g_O);
    cudaGetSymbolAddress((void**)&gm, g_m);
    cudaGetSymbolAddress((void**)&gl, g_l);

    float* Z = (float*)d_out;                          // [S,B,E]
    float* attn_avg = (float*)d_out + (long)MROWS*EMB; // [B,S,S]

    // one-time stream/event setup (first call = eager correctness run)
    static cudaStream_t s2 = nullptr;
    static cudaEvent_t evFork = nullptr, evJoin = nullptr;
    if (!s2){
        cudaStreamCreateWithFlags(&s2, cudaStreamNonBlocking);
        cudaEventCreateWithFlags(&evFork, cudaEventDisableTiming);
        cudaEventCreateWithFlags(&evJoin, cudaEventDisableTiming);
        cudaFuncSetAttribute(avg_attn, cudaFuncAttributeMaxDynamicSharedMemorySize, 110592);
    }

    // 1) Q/K/V projections merged (Q,K -> permuted tf32 bits)
    dim3 gqkv(EMB/128, MROWS/64, 3);
    qkv_proj<<<gqkv, 256>>>(query, key, value, q_w, q_b, k_w, k_b, v_w, v_b, qp, kp, vp);

    // 2) Flash attention
    dim3 gfa(NHEADS, S_LEN/128, 1);
    flash_attn<<<gfa, 128>>>(qp, kp, vp, op, gm, gl);

    // fork: out_proj on s2 concurrent with avg_attn on main stream
    cudaEventRecord(evFork, 0);
    cudaStreamWaitEvent(s2, evFork, 0);

    dim3 gop(EMB/128, MROWS/64, 1);
    out_proj<<<gop, 256, 0, s2>>>(op, out_w, out_b, Z);
    cudaEventRecord(evJoin, s2);

    dim3 gav(S_LEN/64, S_LEN/128, BSZ);
    avg_attn<<<gav, 256, 110592>>>(qp, kp, gm, gl, attn_avg);

    // join
    cudaStreamWaitEvent(0, evJoin, 0);
}

// round 10
// speedup vs baseline: 1.0991x; 1.0991x over previous
#include <cuda_runtime.h>

#define S_LEN 2048
#define BSZ   2
#define EMB   1024
#define NH    16
#define DH    64
#define MROWS 4096
#define NHEADS 32
#define S2 ((long)S_LEN*S_LEN)
#define LOG2E 1.4426950408889634f

// Scratch (__device__ globals per alloc-free rule)
__device__ float g_Qp[MROWS*EMB];   // column-pair-permuted, RNA tf32 bits
__device__ float g_Kp[MROWS*EMB];   // column-pair-permuted, RNA tf32 bits
__device__ float g_Vp[MROWS*EMB];   // normal layout, fp32
__device__ float g_O [MROWS*EMB];
__device__ float g_m [NHEADS*S_LEN];
__device__ float g_l [NHEADS*S_LEN];

__device__ __forceinline__ unsigned f2tf(float f){
    unsigned u; asm("cvt.rna.tf32.f32 %0, %1;" : "=r"(u) : "f"(f)); return u;
}
__device__ __forceinline__ void mma8(float* c, const unsigned* a, const unsigned* b){
    asm volatile("mma.sync.aligned.m16n8k8.row.col.f32.tf32.tf32.f32 "
      "{%0,%1,%2,%3}, {%4,%5,%6,%7}, {%8,%9}, {%0,%1,%2,%3};\n"
      : "+f"(c[0]), "+f"(c[1]), "+f"(c[2]), "+f"(c[3])
      : "r"(a[0]), "r"(a[1]), "r"(a[2]), "r"(a[3]), "r"(b[0]), "r"(b[1]));
}
__device__ __forceinline__ void cpa16(void* dst, const void* src){
    unsigned d = (unsigned)__cvta_generic_to_shared(dst);
    asm volatile("cp.async.cg.shared.global [%0], [%1], 16;\n" :: "r"(d), "l"(src));
}

// ---------------------------------------------------------------------------
// TN tf32 GEMM body (round-8 proven structure). permOut: C written
// column-pair-permuted AND as RNA tf32 bits for flash/avg consumers.
// ---------------------------------------------------------------------------
template<int BM,int BN,int BK,int WM,int WN,int NWARPS>
__device__ __forceinline__
void gemm_body(const float* __restrict__ A, int lda,
               const float* __restrict__ B, int ldb,
               float* __restrict__ C, int ldc,
               const float* __restrict__ bias, float scale, int K,
               int m0, int n0, bool permOut)
{
    constexpr int NT  = NWARPS*32;
    constexpr int LA  = BM*BK/(NT*4);
    constexpr int LB  = BN*BK/(NT*4);
    constexpr int WGN = BN/WN;
    constexpr int MI  = WM/16, NI = WN/8;
    constexpr int LDS_ = BK + 4;

    __shared__ unsigned As[2][BM][LDS_];
    __shared__ unsigned Bs[2][BN][LDS_];

    const int tid  = threadIdx.x;
    const int lane = tid & 31, wid = tid >> 5;
    const int wm = wid / WGN, wn = wid % WGN;

    float acc[MI][NI][4] = {};
    float4 ra[LA], rb[LB];

    auto ldtiles = [&](int k0){
        #pragma unroll
        for (int i = 0; i < LA; ++i){
            int idx = tid + i*NT;
            int r = idx / (BK/4), c = (idx % (BK/4)) * 4;
            ra[i] = *(const float4*)(A + (long)(m0+r)*lda + k0 + c);
        }
        #pragma unroll
        for (int i = 0; i < LB; ++i){
            int idx = tid + i*NT;
            int r = idx / (BK/4), c = (idx % (BK/4)) * 4;
            rb[i] = *(const float4*)(B + (long)(n0+r)*ldb + k0 + c);
        }
    };
    auto sttiles = [&](int buf){
        #pragma unroll
        for (int i = 0; i < LA; ++i){
            int idx = tid + i*NT;
            int r = idx / (BK/4), c = (idx % (BK/4)) * 4;
            uint4 u = { f2tf(ra[i].x), f2tf(ra[i].y), f2tf(ra[i].z), f2tf(ra[i].w) };
            *(uint4*)&As[buf][r][c] = u;
        }
        #pragma unroll
        for (int i = 0; i < LB; ++i){
            int idx = tid + i*NT;
            int r = idx / (BK/4), c = (idx % (BK/4)) * 4;
            uint4 u = { f2tf(rb[i].x), f2tf(rb[i].y), f2tf(rb[i].z), f2tf(rb[i].w) };
            *(uint4*)&Bs[buf][r][c] = u;
        }
    };
    auto compute = [&](int buf){
        #pragma unroll
        for (int ks = 0; ks < BK/8; ++ks){
            unsigned af[MI][4], bf[NI][2];
            #pragma unroll
            for (int mi = 0; mi < MI; ++mi){
                int m = wm*WM + mi*16 + (lane>>2);
                int k = ks*8 + (lane&3);
                af[mi][0] = As[buf][m  ][k  ];
                af[mi][1] = As[buf][m+8][k  ];
                af[mi][2] = As[buf][m  ][k+4];
                af[mi][3] = As[buf][m+8][k+4];
            }
            #pragma unroll
            for (int ni = 0; ni < NI; ++ni){
                int n = wn*WN + ni*8 + (lane>>2);
                int k = ks*8 + (lane&3);
                bf[ni][0] = Bs[buf][n][k  ];
                bf[ni][1] = Bs[buf][n][k+4];
            }
            #pragma unroll
            for (int mi = 0; mi < MI; ++mi)
                #pragma unroll
                for (int ni = 0; ni < NI; ++ni)
                    mma8(acc[mi][ni], af[mi], bf[ni]);
        }
    };

    ldtiles(0); sttiles(0); __syncthreads();
    const int nk = K/BK;
    for (int t = 1; t < nk; ++t){
        ldtiles(t*BK);
        compute((t-1)&1);
        sttiles(t&1);
        __syncthreads();
    }
    compute((nk-1)&1);

    #pragma unroll
    for (int mi = 0; mi < MI; ++mi){
        #pragma unroll
        for (int ni = 0; ni < NI; ++ni){
            int m = m0 + wm*WM + mi*16 + (lane>>2);
            int n = n0 + wn*WN + ni*8 + 2*(lane&3);
            float v0 = acc[mi][ni][0], v1 = acc[mi][ni][1];
            float v2 = acc[mi][ni][2], v3 = acc[mi][ni][3];
            float b0 = bias[n], b1 = bias[n+1];
            v0 = (v0+b0)*scale; v1 = (v1+b1)*scale;
            v2 = (v2+b0)*scale; v3 = (v3+b1)*scale;
            if (permOut){
                int p0 = (n & ~7) | ((n&3)<<1) | ((n>>2)&1);   // perm(n); perm(n+1)=p0+2
                C[(long)m    *ldc + p0    ] = __uint_as_float(f2tf(v0));
                C[(long)m    *ldc + p0 + 2] = __uint_as_float(f2tf(v1));
                C[(long)(m+8)*ldc + p0    ] = __uint_as_float(f2tf(v2));
                C[(long)(m+8)*ldc + p0 + 2] = __uint_as_float(f2tf(v3));
            } else {
                *(float2*)(C + (long)m    *ldc + n) = make_float2(v0, v1);
                *(float2*)(C + (long)(m+8)*ldc + n) = make_float2(v2, v3);
            }
        }
    }
}

// Merged Q/K/V projections: grid (8, 64, 3). Q,K -> permuted tf32 bits.
__global__ __launch_bounds__(256)
void qkv_proj(const float* __restrict__ q, const float* __restrict__ k, const float* __restrict__ v,
              const float* __restrict__ qw, const float* __restrict__ qb,
              const float* __restrict__ kw, const float* __restrict__ kb,
              const float* __restrict__ vw, const float* __restrict__ vb,
              float* __restrict__ qp, float* __restrict__ kp, float* __restrict__ vp)
{
    const int z = blockIdx.z;
    const float* A  = (z==0)? q  : (z==1)? k  : v;
    const float* W  = (z==0)? qw : (z==1)? kw : vw;
    const float* bi = (z==0)? qb : (z==1)? kb : vb;
    float*       C  = (z==0)? qp : (z==1)? kp : vp;
    const float scale = (z==0)? 0.125f : 1.0f;
    gemm_body<64,128,16,32,32,8>(A, EMB, W, EMB, C, EMB, bi, scale, EMB,
                                 blockIdx.y*64, blockIdx.x*128, z<2);
}

// Output projection: grid (8, 64)
__global__ __launch_bounds__(256)
void out_proj(const float* __restrict__ A, const float* __restrict__ W,
              const float* __restrict__ bi, float* __restrict__ C)
{
    gemm_body<64,128,16,32,32,8>(A, EMB, W, EMB, C, EMB, bi, 1.0f, EMB,
                                 blockIdx.y*64, blockIdx.x*128, false);
}

// ---------------------------------------------------------------------------
// Flash attention: q-tile 128, 4 warps (MI=2), k-tiles 32 double-buffered.
// Q/K arrive as permuted tf32 bits -> fragment loads are plain LDS.64.
// ---------------------------------------------------------------------------
__global__ __launch_bounds__(128)
void flash_attn(const float* __restrict__ qp, const float* __restrict__ kp,
                const float* __restrict__ vp, float* __restrict__ op,
                float* __restrict__ gm, float* __restrict__ gl)
{
    __shared__ __align__(16) unsigned SU[9216];
    const int tid = threadIdx.x, lane = tid&31, w = tid>>5;
    const int hb = blockIdx.x, h = hb&15, b = hb>>4;
    const int q0 = blockIdx.y*128;
    const long base = (long)b*EMB + h*DH;
    const float* Qg = qp + base + (long)q0*(BSZ*EMB);
    const float* Kg = kp + base;
    const float* Vg = vp + base;

    // stage Q (already tf32 bits, permuted)
    for (int i = tid; i < 2048; i += 128){
        int r = i>>4, c = (i&15)*4;
        cpa16(&SU[r*72 + c], Qg + (long)r*(BSZ*EMB) + c);
    }
    asm volatile("cp.async.commit_group;\n");
    asm volatile("cp.async.wait_group 0;\n");
    __syncthreads();

    unsigned Qa[8][2][4];
    {
        const int p = lane>>2, col0 = 2*(lane&3);
        #pragma unroll
        for (int ks = 0; ks < 8; ++ks)
            #pragma unroll
            for (int mi = 0; mi < 2; ++mi){
                int m = w*32 + mi*16 + p;
                int col = ks*8 + col0;
                uint2 u0 = *(const uint2*)&SU[ m   *72 + col];
                uint2 u1 = *(const uint2*)&SU[(m+8)*72 + col];
                Qa[ks][mi][0] = u0.x; Qa[ks][mi][1] = u1.x;
                Qa[ks][mi][2] = u0.y; Qa[ks][mi][3] = u1.y;
            }
    }
    __syncthreads();

    unsigned* const Kb0 = SU;
    unsigned* const Kb1 = SU + 2304;
    unsigned* const Vb0 = SU + 4608;
    unsigned* const Vb1 = SU + 6912;

    auto load_kv = [&](int kt, int sel){
        unsigned* Kb = sel ? Kb1 : Kb0;
        unsigned* Vb = sel ? Vb1 : Vb0;
        const long r0 = (long)kt*32;
        #pragma unroll
        for (int j = 0; j < 4; ++j){
            int cch = tid + j*128;
            int r = cch>>4, cc = (cch&15)*4;
            cpa16(&Kb[r*72 + cc], Kg + (r0+r)*(BSZ*EMB) + cc);
            cpa16(&Vb[r*72 + cc], Vg + (r0+r)*(BSZ*EMB) + cc);
        }
    };

    float m_[2][2] = {{-1e30f,-1e30f},{-1e30f,-1e30f}};
    float l_[2][2] = {};
    float o[2][8][4] = {};

    const int srcA = (lane & ~3) | ((lane&3)>>1);
    const int srcB = srcA + 2;
    const bool osel = (lane & 1);

    load_kv(0, 0);
    asm volatile("cp.async.commit_group;\n");

    for (int t = 0; t < 64; ++t){
        if (t < 63){
            load_kv(t+1, (t+1)&1);
            asm volatile("cp.async.commit_group;\n");
            asm volatile("cp.async.wait_group 1;\n");
        } else {
            asm volatile("cp.async.wait_group 0;\n");
        }
        __syncthreads();

        unsigned* Kb = (t&1) ? Kb1 : Kb0;
        unsigned* Vb = (t&1) ? Vb1 : Vb0;

        // S = Q K^T  (K fragments via plain LDS.64)
        float c_[2][4][4] = {};
        #pragma unroll
        for (int ks = 0; ks < 8; ++ks){
            unsigned bf[4][2];
            #pragma unroll
            for (int ni = 0; ni < 4; ++ni){
                int n = ni*8 + (lane>>2);
                int col = ks*8 + 2*(lane&3);
                uint2 u = *(const uint2*)&Kb[n*72 + col];
                bf[ni][0] = u.x; bf[ni][1] = u.y;
            }
            #pragma unroll
            for (int mi = 0; mi < 2; ++mi)
                #pragma unroll
                for (int ni = 0; ni < 4; ++ni)
                    mma8(c_[mi][ni], Qa[ks][mi], bf[ni]);
        }

        // online softmax with rescale-skip
        #pragma unroll
        for (int mi = 0; mi < 2; ++mi){
            float mx0 = -1e30f, mx1 = -1e30f;
            #pragma unroll
            for (int ni = 0; ni < 4; ++ni){
                mx0 = fmaxf(mx0, fmaxf(c_[mi][ni][0], c_[mi][ni][1]));
                mx1 = fmaxf(mx1, fmaxf(c_[mi][ni][2], c_[mi][ni][3]));
            }
            mx0 = fmaxf(mx0, __shfl_xor_sync(0xffffffffu, mx0, 1));
            mx0 = fmaxf(mx0, __shfl_xor_sync(0xffffffffu, mx0, 2));
            mx1 = fmaxf(mx1, __shfl_xor_sync(0xffffffffu, mx1, 1));
            mx1 = fmaxf(mx1, __shfl_xor_sync(0xffffffffu, mx1, 2));
            float mn0 = fmaxf(m_[mi][0], mx0), mn1 = fmaxf(m_[mi][1], mx1);
            if (!__all_sync(0xffffffffu, (mn0 == m_[mi][0]) & (mn1 == m_[mi][1]))){
                float f0 = __expf(m_[mi][0] - mn0), f1 = __expf(m_[mi][1] - mn1);
                l_[mi][0] *= f0; l_[mi][1] *= f1;
                #pragma unroll
                for (int ni = 0; ni < 8; ++ni){
                    o[mi][ni][0]*=f0; o[mi][ni][1]*=f0;
                    o[mi][ni][2]*=f1; o[mi][ni][3]*=f1;
                }
                m_[mi][0] = mn0; m_[mi][1] = mn1;
            }
            float s0 = 0.f, s1 = 0.f;
            #pragma unroll
            for (int ni = 0; ni < 4; ++ni){
                c_[mi][ni][0] = __expf(c_[mi][ni][0]-m_[mi][0]);
                c_[mi][ni][1] = __expf(c_[mi][ni][1]-m_[mi][0]);
                c_[mi][ni][2] = __expf(c_[mi][ni][2]-m_[mi][1]);
                c_[mi][ni][3] = __expf(c_[mi][ni][3]-m_[mi][1]);
                s0 += c_[mi][ni][0]+c_[mi][ni][1];
                s1 += c_[mi][ni][2]+c_[mi][ni][3];
            }
            s0 += __shfl_xor_sync(0xffffffffu, s0, 1);
            s0 += __shfl_xor_sync(0xffffffffu, s0, 2);
            s1 += __shfl_xor_sync(0xffffffffu, s1, 1);
            s1 += __shfl_xor_sync(0xffffffffu, s1, 2);
            l_[mi][0] += s0; l_[mi][1] += s1;
        }

        // P @ V
        #pragma unroll
        for (int ks2 = 0; ks2 < 4; ++ks2){
            unsigned a[2][4];
            #pragma unroll
            for (int mi = 0; mi < 2; ++mi){
                float v00 = __shfl_sync(0xffffffffu, c_[mi][ks2][0], srcA);
                float v01 = __shfl_sync(0xffffffffu, c_[mi][ks2][1], srcA);
                float v10 = __shfl_sync(0xffffffffu, c_[mi][ks2][2], srcA);
                float v11 = __shfl_sync(0xffffffffu, c_[mi][ks2][3], srcA);
                float v40 = __shfl_sync(0xffffffffu, c_[mi][ks2][0], srcB);
                float v41 = __shfl_sync(0xffffffffu, c_[mi][ks2][1], srcB);
                float v50 = __shfl_sync(0xffffffffu, c_[mi][ks2][2], srcB);
                float v51 = __shfl_sync(0xffffffffu, c_[mi][ks2][3], srcB);
                a[mi][0] = f2tf(osel ? v01 : v00);
                a[mi][1] = f2tf(osel ? v11 : v10);
                a[mi][2] = f2tf(osel ? v41 : v40);
                a[mi][3] = f2tf(osel ? v51 : v50);
            }
            #pragma unroll
            for (int ni = 0; ni < 8; ++ni){
                int kk = ks2*8 + (lane&3);
                int n  = ni*8 + (lane>>2);
                unsigned bf[2] = { Vb[kk*72 + n], Vb[(kk+4)*72 + n] };
                mma8(o[0][ni], a[0], bf);
                mma8(o[1][ni], a[1], bf);
            }
        }
        __syncthreads();
    }

    float* Og = op + base + (long)q0*(BSZ*EMB);
    #pragma unroll
    for (int mi = 0; mi < 2; ++mi){
        float inv0 = 1.f/l_[mi][0], inv1 = 1.f/l_[mi][1];
        int m = w*32 + mi*16 + (lane>>2);
        #pragma unroll
        for (int ni = 0; ni < 8; ++ni){
            int d = ni*8 + 2*(lane&3);
            *(float2*)(Og + (long)m    *(BSZ*EMB) + d) = make_float2(o[mi][ni][0]*inv0, o[mi][ni][1]*inv0);
            *(float2*)(Og + (long)(m+8)*(BSZ*EMB) + d) = make_float2(o[mi][ni][2]*inv1, o[mi][ni][3]*inv1);
        }
        if ((lane & 3) == 0){
            gm[(long)hb*S_LEN + q0 + m]     = m_[mi][0];
            gm[(long)hb*S_LEN + q0 + m + 8] = m_[mi][1];
            gl[(long)hb*S_LEN + q0 + m]     = l_[mi][0];
            gl[(long)hb*S_LEN + q0 + m + 8] = l_[mi][1];
        }
    }
}

// ---------------------------------------------------------------------------
// attn_avg: 256 thr, k-tile 64, q-tile 128, double-buffered heads.
// Q/K tf32 bits -> plain LDS.64 fragment loads (no cvt).
// Softmax folded: acc += exp2(c*log2e - e), e = m*log2e + log2(l) + 4.
// ---------------------------------------------------------------------------
__global__ __launch_bounds__(256)
void avg_attn(const float* __restrict__ qp, const float* __restrict__ kp,
              const float* __restrict__ gm, const float* __restrict__ gl,
              float* __restrict__ avg)
{
    extern __shared__ __align__(16) unsigned ASH[];
    constexpr int BUF = 128*72 + 64*72;
    const int tid = threadIdx.x, lane = tid&31, wid = tid>>5;
    const int k0 = blockIdx.x*64, q0 = blockIdx.y*128, b = blockIdx.z;
    const int rloc = wid*16 + (lane>>2);

    auto stage = [&](int h, int sel){
        unsigned* Qs = ASH + sel*BUF;
        unsigned* Ks = Qs + 128*72;
        const long base = (long)b*EMB + h*DH;
        #pragma unroll
        for (int j = 0; j < 8; ++j){
            int idx = tid + j*256;
            int r = idx>>4, c = (idx&15)*4;
            cpa16(&Qs[r*72 + c], qp + base + (long)(q0+r)*(BSZ*EMB) + c);
        }
        #pragma unroll
        for (int j = 0; j < 4; ++j){
            int idx = tid + j*256;
            int r = idx>>4, c = (idx&15)*4;
            cpa16(&Ks[r*72 + c], kp + base + (long)(k0+r)*(BSZ*EMB) + c);
        }
        asm volatile("cp.async.commit_group;\n");
    };

    float acc[8][4] = {};

    stage(0, 0);
    for (int h = 0; h < NH; ++h){
        if (h < NH-1){
            stage(h+1, (h+1)&1);
            asm volatile("cp.async.wait_group 1;\n");
        } else {
            asm volatile("cp.async.wait_group 0;\n");
        }
        __syncthreads();

        unsigned* Qs = ASH + (h&1)*BUF;
        unsigned* Ks = Qs + 128*72;

        float c_[8][4] = {};
        #pragma unroll
        for (int ks = 0; ks < 8; ++ks){
            int col = ks*8 + 2*(lane&3);
            uint2 u0 = *(const uint2*)&Qs[ rloc   *72 + col];
            uint2 u1 = *(const uint2*)&Qs[(rloc+8)*72 + col];
            unsigned a[4] = { u0.x, u1.x, u0.y, u1.y };
            #pragma unroll
            for (int ni = 0; ni < 8; ++ni){
                int n = ni*8 + (lane>>2);
                uint2 ub = *(const uint2*)&Ks[n*72 + col];
                unsigned bf[2] = { ub.x, ub.y };
                mma8(c_[ni], a, bf);
            }
        }

        const int hb = b*NH + h;
        // e = m*log2e + log2(l) + 4  (folds exp, 1/l and 1/16 into one FMA+EX2)
        float e0 = gm[(long)hb*S_LEN + q0 + rloc    ]*LOG2E
                 + __log2f(gl[(long)hb*S_LEN + q0 + rloc    ]) + 4.0f;
        float e1 = gm[(long)hb*S_LEN + q0 + rloc + 8]*LOG2E
                 + __log2f(gl[(long)hb*S_LEN + q0 + rloc + 8]) + 4.0f;
        #pragma unroll
        for (int ni = 0; ni < 8; ++ni){
            acc[ni][0] += exp2f(fmaf(c_[ni][0], LOG2E, -e0));
            acc[ni][1] += exp2f(fmaf(c_[ni][1], LOG2E, -e0));
            acc[ni][2] += exp2f(fmaf(c_[ni][2], LOG2E, -e1));
            acc[ni][3] += exp2f(fmaf(c_[ni][3], LOG2E, -e1));
        }
        __syncthreads();
    }

    float* out = avg + (long)b*S2;
    #pragma unroll
    for (int ni = 0; ni < 8; ++ni){
        int kc = k0 + ni*8 + 2*(lane&3);
        *(float2*)(out + (long)(q0+rloc)  *S_LEN + kc) = make_float2(acc[ni][0], acc[ni][1]);
        *(float2*)(out + (long)(q0+rloc+8)*S_LEN + kc) = make_float2(acc[ni][2], acc[ni][3]);
    }
}

// ---------------------------------------------------------------------------
extern "C" void kernel_launch(void* const* d_in, const int* in_sizes, int n_in,
                              void* d_out, int out_size)
{
    const float* query = (const float*)d_in[0];
    const float* key   = (const float*)d_in[1];
    const float* value = (const float*)d_in[2];
    const float* q_w = (const float*)d_in[3];
    const float* q_b = (const float*)d_in[4];
    const float* k_w = (const float*)d_in[5];
    const float* k_b = (const float*)d_in[6];
    const float* v_w = (const float*)d_in[7];
    const float* v_b = (const float*)d_in[8];
    const float* out_w = (const float*)d_in[9];
    const float* out_b = (const float*)d_in[10];

    float *qp, *kp, *vp, *op, *gm, *gl;
    cudaGetSymbolAddress((void**)&qp, g_Qp);
    cudaGetSymbolAddress((void**)&kp, g_Kp);
    cudaGetSymbolAddress((void**)&vp, g_Vp);
    cudaGetSymbolAddress((void**)&op, g_O);
    cudaGetSymbolAddress((void**)&gm, g_m);
    cudaGetSymbolAddress((void**)&gl, g_l);

    float* Z = (float*)d_out;                          // [S,B,E]
    float* attn_avg = (float*)d_out + (long)MROWS*EMB; // [B,S,S]

    // one-time stream/event setup (first call = eager correctness run)
    static cudaStream_t s2 = nullptr;
    static cudaEvent_t evFork = nullptr, evJoin = nullptr;
    if (!s2){
        cudaStreamCreateWithFlags(&s2, cudaStreamNonBlocking);
        cudaEventCreateWithFlags(&evFork, cudaEventDisableTiming);
        cudaEventCreateWithFlags(&evJoin, cudaEventDisableTiming);
        cudaFuncSetAttribute(avg_attn, cudaFuncAttributeMaxDynamicSharedMemorySize, 110592);
    }

    // 1) Q/K/V projections merged (Q,K -> permuted tf32 bits)
    dim3 gqkv(EMB/128, MROWS/64, 3);
    qkv_proj<<<gqkv, 256>>>(query, key, value, q_w, q_b, k_w, k_b, v_w, v_b, qp, kp, vp);

    // 2) Flash attention
    dim3 gfa(NHEADS, S_LEN/128, 1);
    flash_attn<<<gfa, 128>>>(qp, kp, vp, op, gm, gl);

    // fork: out_proj on s2 concurrent with avg_attn on main stream
    cudaEventRecord(evFork, 0);
    cudaStreamWaitEvent(s2, evFork, 0);

    dim3 gop(EMB/128, MROWS/64, 1);
    out_proj<<<gop, 256, 0, s2>>>(op, out_w, out_b, Z);
    cudaEventRecord(evJoin, s2);

    dim3 gav(S_LEN/64, S_LEN/128, BSZ);
    avg_attn<<<gav, 256, 110592>>>(qp, kp, gm, gl, attn_avg);

    // join
    cudaStreamWaitEvent(0, evJoin, 0);
}

// round 11
// speedup vs baseline: 1.1548x; 1.0507x over previous
#include <cuda_runtime.h>
#include <cuda_fp16.h>

#define S_LEN 2048
#define BSZ   2
#define EMB   1024
#define NH    16
#define DH    64
#define MROWS 4096
#define NHEADS 32
#define S2 ((long)S_LEN*S_LEN)
#define LOG2E 1.4426950408889634f

// Scratch (__device__ globals per alloc-free rule)
__device__ float g_Qp[MROWS*EMB];   // column-pair-permuted, RNA tf32 bits
__device__ float g_Kp[MROWS*EMB];   // column-pair-permuted, RNA tf32 bits
__device__ float g_Vp[MROWS*EMB];   // normal layout, fp32 [m][1024]
__device__ __half g_Vh[(size_t)MROWS*EMB];  // transposed fp16: row (hb*64+d), col s (2048 half)
__device__ float g_O [MROWS*EMB];
__device__ float g_m [NHEADS*S_LEN];
__device__ float g_l [NHEADS*S_LEN];

__device__ __forceinline__ unsigned f2tf(float f){
    unsigned u; asm("cvt.rna.tf32.f32 %0, %1;" : "=r"(u) : "f"(f)); return u;
}
__device__ __forceinline__ unsigned packh2(float lo, float hi){
    __half2 h = __floats2half2_rn(lo, hi);
    return *(unsigned*)&h;
}
__device__ __forceinline__ void mma8(float* c, const unsigned* a, const unsigned* b){
    asm volatile("mma.sync.aligned.m16n8k8.row.col.f32.tf32.tf32.f32 "
      "{%0,%1,%2,%3}, {%4,%5,%6,%7}, {%8,%9}, {%0,%1,%2,%3};\n"
      : "+f"(c[0]), "+f"(c[1]), "+f"(c[2]), "+f"(c[3])
      : "r"(a[0]), "r"(a[1]), "r"(a[2]), "r"(a[3]), "r"(b[0]), "r"(b[1]));
}
__device__ __forceinline__ void mma16f16(float* c, const unsigned* a, unsigned b0, unsigned b1){
    asm volatile("mma.sync.aligned.m16n8k16.row.col.f32.f16.f16.f32 "
      "{%0,%1,%2,%3}, {%4,%5,%6,%7}, {%8,%9}, {%0,%1,%2,%3};\n"
      : "+f"(c[0]), "+f"(c[1]), "+f"(c[2]), "+f"(c[3])
      : "r"(a[0]), "r"(a[1]), "r"(a[2]), "r"(a[3]), "r"(b0), "r"(b1));
}
__device__ __forceinline__ void cpa16(void* dst, const void* src){
    unsigned d = (unsigned)__cvta_generic_to_shared(dst);
    asm volatile("cp.async.cg.shared.global [%0], [%1], 16;\n" :: "r"(d), "l"(src));
}

// ---------------------------------------------------------------------------
// TN tf32 GEMM body (round-8 proven structure). permOut: C written
// column-pair-permuted AND as RNA tf32 bits for flash/avg consumers.
// ---------------------------------------------------------------------------
template<int BM,int BN,int BK,int WM,int WN,int NWARPS>
__device__ __forceinline__
void gemm_body(const float* __restrict__ A, int lda,
               const float* __restrict__ B, int ldb,
               float* __restrict__ C, int ldc,
               const float* __restrict__ bias, float scale, int K,
               int m0, int n0, bool permOut)
{
    constexpr int NT  = NWARPS*32;
    constexpr int LA  = BM*BK/(NT*4);
    constexpr int LB  = BN*BK/(NT*4);
    constexpr int WGN = BN/WN;
    constexpr int MI  = WM/16, NI = WN/8;
    constexpr int LDS_ = BK + 4;

    __shared__ unsigned As[2][BM][LDS_];
    __shared__ unsigned Bs[2][BN][LDS_];

    const int tid  = threadIdx.x;
    const int lane = tid & 31, wid = tid >> 5;
    const int wm = wid / WGN, wn = wid % WGN;

    float acc[MI][NI][4] = {};
    float4 ra[LA], rb[LB];

    auto ldtiles = [&](int k0){
        #pragma unroll
        for (int i = 0; i < LA; ++i){
            int idx = tid + i*NT;
            int r = idx / (BK/4), c = (idx % (BK/4)) * 4;
            ra[i] = *(const float4*)(A + (long)(m0+r)*lda + k0 + c);
        }
        #pragma unroll
        for (int i = 0; i < LB; ++i){
            int idx = tid + i*NT;
            int r = idx / (BK/4), c = (idx % (BK/4)) * 4;
            rb[i] = *(const float4*)(B + (long)(n0+r)*ldb + k0 + c);
        }
    };
    auto sttiles = [&](int buf){
        #pragma unroll
        for (int i = 0; i < LA; ++i){
            int idx = tid + i*NT;
            int r = idx / (BK/4), c = (idx % (BK/4)) * 4;
            uint4 u = { f2tf(ra[i].x), f2tf(ra[i].y), f2tf(ra[i].z), f2tf(ra[i].w) };
            *(uint4*)&As[buf][r][c] = u;
        }
        #pragma unroll
        for (int i = 0; i < LB; ++i){
            int idx = tid + i*NT;
            int r = idx / (BK/4), c = (idx % (BK/4)) * 4;
            uint4 u = { f2tf(rb[i].x), f2tf(rb[i].y), f2tf(rb[i].z), f2tf(rb[i].w) };
            *(uint4*)&Bs[buf][r][c] = u;
        }
    };
    auto compute = [&](int buf){
        #pragma unroll
        for (int ks = 0; ks < BK/8; ++ks){
            unsigned af[MI][4], bf[NI][2];
            #pragma unroll
            for (int mi = 0; mi < MI; ++mi){
                int m = wm*WM + mi*16 + (lane>>2);
                int k = ks*8 + (lane&3);
                af[mi][0] = As[buf][m  ][k  ];
                af[mi][1] = As[buf][m+8][k  ];
                af[mi][2] = As[buf][m  ][k+4];
                af[mi][3] = As[buf][m+8][k+4];
            }
            #pragma unroll
            for (int ni = 0; ni < NI; ++ni){
                int n = wn*WN + ni*8 + (lane>>2);
                int k = ks*8 + (lane&3);
                bf[ni][0] = Bs[buf][n][k  ];
                bf[ni][1] = Bs[buf][n][k+4];
            }
            #pragma unroll
            for (int mi = 0; mi < MI; ++mi)
                #pragma unroll
                for (int ni = 0; ni < NI; ++ni)
                    mma8(acc[mi][ni], af[mi], bf[ni]);
        }
    };

    ldtiles(0); sttiles(0); __syncthreads();
    const int nk = K/BK;
    for (int t = 1; t < nk; ++t){
        ldtiles(t*BK);
        compute((t-1)&1);
        sttiles(t&1);
        __syncthreads();
    }
    compute((nk-1)&1);

    #pragma unroll
    for (int mi = 0; mi < MI; ++mi){
        #pragma unroll
        for (int ni = 0; ni < NI; ++ni){
            int m = m0 + wm*WM + mi*16 + (lane>>2);
            int n = n0 + wn*WN + ni*8 + 2*(lane&3);
            float v0 = acc[mi][ni][0], v1 = acc[mi][ni][1];
            float v2 = acc[mi][ni][2], v3 = acc[mi][ni][3];
            float b0 = bias[n], b1 = bias[n+1];
            v0 = (v0+b0)*scale; v1 = (v1+b1)*scale;
            v2 = (v2+b0)*scale; v3 = (v3+b1)*scale;
            if (permOut){
                int p0 = (n & ~7) | ((n&3)<<1) | ((n>>2)&1);   // perm(n); perm(n+1)=p0+2
                C[(long)m    *ldc + p0    ] = __uint_as_float(f2tf(v0));
                C[(long)m    *ldc + p0 + 2] = __uint_as_float(f2tf(v1));
                C[(long)(m+8)*ldc + p0    ] = __uint_as_float(f2tf(v2));
                C[(long)(m+8)*ldc + p0 + 2] = __uint_as_float(f2tf(v3));
            } else {
                *(float2*)(C + (long)m    *ldc + n) = make_float2(v0, v1);
                *(float2*)(C + (long)(m+8)*ldc + n) = make_float2(v2, v3);
            }
        }
    }
}

// Merged Q/K/V projections: grid (8, 64, 3). Q,K -> permuted tf32 bits.
__global__ __launch_bounds__(256)
void qkv_proj(const float* __restrict__ q, const float* __restrict__ k, const float* __restrict__ v,
              const float* __restrict__ qw, const float* __restrict__ qb,
              const float* __restrict__ kw, const float* __restrict__ kb,
              const float* __restrict__ vw, const float* __restrict__ vb,
              float* __restrict__ qp, float* __restrict__ kp, float* __restrict__ vp)
{
    const int z = blockIdx.z;
    const float* A  = (z==0)? q  : (z==1)? k  : v;
    const float* W  = (z==0)? qw : (z==1)? kw : vw;
    const float* bi = (z==0)? qb : (z==1)? kb : vb;
    float*       C  = (z==0)? qp : (z==1)? kp : vp;
    const float scale = (z==0)? 0.125f : 1.0f;
    gemm_body<64,128,16,32,32,8>(A, EMB, W, EMB, C, EMB, bi, scale, EMB,
                                 blockIdx.y*64, blockIdx.x*128, z<2);
}

// Output projection: grid (8, 64)
__global__ __launch_bounds__(256)
void out_proj(const float* __restrict__ A, const float* __restrict__ W,
              const float* __restrict__ bi, float* __restrict__ C)
{
    gemm_body<64,128,16,32,32,8>(A, EMB, W, EMB, C, EMB, bi, 1.0f, EMB,
                                 blockIdx.y*64, blockIdx.x*128, false);
}

// ---------------------------------------------------------------------------
// V transpose+convert: vp fp32 [m=s*2+b][1024] -> vh half, row (hb*64+d) of
// 2048 half (col = token s). grid (32 s-chunks, 32 hb), 256 thr. ~25MB traffic.
// ---------------------------------------------------------------------------
__global__ __launch_bounds__(256)
void v_transpose(const float* __restrict__ vp, unsigned* __restrict__ vh2)
{
    __shared__ float T[64][65];
    const int tid = threadIdx.x;
    const int hb = blockIdx.y, h = hb&15, b = hb>>4;
    const int s0 = blockIdx.x*64;

    // load 64 tokens x 64 dims (coalesced float4 rows)
    #pragma unroll
    for (int i = 0; i < 4; ++i){
        int idx = tid + i*256;              // 0..1023 units of 4
        int si = idx>>4, d4 = (idx&15)*4;
        float4 u = *(const float4*)(vp + (long)((s0+si)*2 + b)*EMB + h*64 + d4);
        T[si][d4+0]=u.x; T[si][d4+1]=u.y; T[si][d4+2]=u.z; T[si][d4+3]=u.w;
    }
    __syncthreads();

    // write: per d row, 32 half2 (token pairs), coalesced
    #pragma unroll
    for (int j = 0; j < 8; ++j){
        int w = tid + j*256;                // 0..2047
        int d = w>>5, sp = w&31;
        unsigned val = packh2(T[2*sp][d], T[2*sp+1][d]);
        vh2[(long)(hb*64 + d)*1024 + (s0>>1) + sp] = val;
    }
}

// ---------------------------------------------------------------------------
// Flash attention: q-tile 128, 4 warps (MI=2), k-tiles 32 double-buffered.
// QK^T in tf32 (permuted-bit layout, LDS.64 frags). PV in fp16 m16n8k16:
// S C-frags pack directly to A-frags (NO shuffles); V staged as half2
// [d][k/2] stride 20 (all-32-bank fragment reads), cp.async from g_Vh.
// ---------------------------------------------------------------------------
__global__ __launch_bounds__(128)
void flash_attn(const float* __restrict__ qp, const float* __restrict__ kp,
                const __half* __restrict__ vh, float* __restrict__ op,
                float* __restrict__ gm, float* __restrict__ gl)
{
    __shared__ __align__(16) unsigned SU[9216];
    const int tid = threadIdx.x, lane = tid&31, w = tid>>5;
    const int hb = blockIdx.x, h = hb&15, b = hb>>4;
    const int q0 = blockIdx.y*128;
    const long base = (long)b*EMB + h*DH;
    const float* Qg = qp + base + (long)q0*(BSZ*EMB);
    const float* Kg = kp + base;
    const __half* Vgh = vh + (long)hb*64*2048;   // row d: 2048 half

    // stage Q (tf32 bits, permuted)
    for (int i = tid; i < 2048; i += 128){
        int r = i>>4, c = (i&15)*4;
        cpa16(&SU[r*72 + c], Qg + (long)r*(BSZ*EMB) + c);
    }
    asm volatile("cp.async.commit_group;\n");
    asm volatile("cp.async.wait_group 0;\n");
    __syncthreads();

    unsigned Qa[8][2][4];
    {
        const int p = lane>>2, col0 = 2*(lane&3);
        #pragma unroll
        for (int ks = 0; ks < 8; ++ks)
            #pragma unroll
            for (int mi = 0; mi < 2; ++mi){
                int m = w*32 + mi*16 + p;
                int col = ks*8 + col0;
                uint2 u0 = *(const uint2*)&SU[ m   *72 + col];
                uint2 u1 = *(const uint2*)&SU[(m+8)*72 + col];
                Qa[ks][mi][0] = u0.x; Qa[ks][mi][1] = u1.x;
                Qa[ks][mi][2] = u0.y; Qa[ks][mi][3] = u1.y;
            }
    }
    __syncthreads();

    unsigned* const Kb0 = SU;
    unsigned* const Kb1 = SU + 2304;     // 32*72
    unsigned* const Vh0 = SU + 4608;     // 64*20 = 1280 words
    unsigned* const Vh1 = SU + 5888;

    auto load_kv = [&](int kt, int sel){
        unsigned* Kb = sel ? Kb1 : Kb0;
        unsigned* Vb = sel ? Vh1 : Vh0;
        const long r0 = (long)kt*32;
        #pragma unroll
        for (int j = 0; j < 4; ++j){
            int cch = tid + j*128;            // K: 512 16B units
            int r = cch>>4, cc = (cch&15)*4;
            cpa16(&Kb[r*72 + cc], Kg + (r0+r)*(BSZ*EMB) + cc);
        }
        #pragma unroll
        for (int j = 0; j < 2; ++j){
            int u = tid + j*128;              // V: 256 16B units
            int d = u>>2, qc = u&3;
            cpa16(&Vb[d*20 + qc*4], Vgh + (long)d*2048 + kt*32 + qc*8);
        }
    };

    float m_[2][2] = {{-1e30f,-1e30f},{-1e30f,-1e30f}};
    float l_[2][2] = {};
    float o[2][8][4] = {};

    load_kv(0, 0);
    asm volatile("cp.async.commit_group;\n");

    for (int t = 0; t < 64; ++t){
        if (t < 63){
            load_kv(t+1, (t+1)&1);
            asm volatile("cp.async.commit_group;\n");
            asm volatile("cp.async.wait_group 1;\n");
        } else {
            asm volatile("cp.async.wait_group 0;\n");
        }
        __syncthreads();

        unsigned* Kb = (t&1) ? Kb1 : Kb0;
        unsigned* Vb = (t&1) ? Vh1 : Vh0;

        // S = Q K^T  (tf32, K frags via LDS.64)
        float c_[2][4][4] = {};
        #pragma unroll
        for (int ks = 0; ks < 8; ++ks){
            unsigned bf[4][2];
            #pragma unroll
            for (int ni = 0; ni < 4; ++ni){
                int n = ni*8 + (lane>>2);
                int col = ks*8 + 2*(lane&3);
                uint2 u = *(const uint2*)&Kb[n*72 + col];
                bf[ni][0] = u.x; bf[ni][1] = u.y;
            }
            #pragma unroll
            for (int mi = 0; mi < 2; ++mi)
                #pragma unroll
                for (int ni = 0; ni < 4; ++ni)
                    mma8(c_[mi][ni], Qa[ks][mi], bf[ni]);
        }

        // online softmax with rescale-skip
        #pragma unroll
        for (int mi = 0; mi < 2; ++mi){
            float mx0 = -1e30f, mx1 = -1e30f;
            #pragma unroll
            for (int ni = 0; ni < 4; ++ni){
                mx0 = fmaxf(mx0, fmaxf(c_[mi][ni][0], c_[mi][ni][1]));
                mx1 = fmaxf(mx1, fmaxf(c_[mi][ni][2], c_[mi][ni][3]));
            }
            mx0 = fmaxf(mx0, __shfl_xor_sync(0xffffffffu, mx0, 1));
            mx0 = fmaxf(mx0, __shfl_xor_sync(0xffffffffu, mx0, 2));
            mx1 = fmaxf(mx1, __shfl_xor_sync(0xffffffffu, mx1, 1));
            mx1 = fmaxf(mx1, __shfl_xor_sync(0xffffffffu, mx1, 2));
            float mn0 = fmaxf(m_[mi][0], mx0), mn1 = fmaxf(m_[mi][1], mx1);
            if (!__all_sync(0xffffffffu, (mn0 == m_[mi][0]) & (mn1 == m_[mi][1]))){
                float f0 = __expf(m_[mi][0] - mn0), f1 = __expf(m_[mi][1] - mn1);
                l_[mi][0] *= f0; l_[mi][1] *= f1;
                #pragma unroll
                for (int ni = 0; ni < 8; ++ni){
                    o[mi][ni][0]*=f0; o[mi][ni][1]*=f0;
                    o[mi][ni][2]*=f1; o[mi][ni][3]*=f1;
                }
                m_[mi][0] = mn0; m_[mi][1] = mn1;
            }
            float s0 = 0.f, s1 = 0.f;
            #pragma unroll
            for (int ni = 0; ni < 4; ++ni){
                c_[mi][ni][0] = __expf(c_[mi][ni][0]-m_[mi][0]);
                c_[mi][ni][1] = __expf(c_[mi][ni][1]-m_[mi][0]);
                c_[mi][ni][2] = __expf(c_[mi][ni][2]-m_[mi][1]);
                c_[mi][ni][3] = __expf(c_[mi][ni][3]-m_[mi][1]);
                s0 += c_[mi][ni][0]+c_[mi][ni][1];
                s1 += c_[mi][ni][2]+c_[mi][ni][3];
            }
            s0 += __shfl_xor_sync(0xffffffffu, s0, 1);
            s0 += __shfl_xor_sync(0xffffffffu, s0, 2);
            s1 += __shfl_xor_sync(0xffffffffu, s1, 1);
            s1 += __shfl_xor_sync(0xffffffffu, s1, 2);
            l_[mi][0] += s0; l_[mi][1] += s1;
        }

        // P @ V in fp16: C-frags pack straight into m16n8k16 A-frags (no shuffles)
        #pragma unroll
        for (int j = 0; j < 2; ++j){
            unsigned a[2][4];
            #pragma unroll
            for (int mi = 0; mi < 2; ++mi){
                a[mi][0] = packh2(c_[mi][2*j  ][0], c_[mi][2*j  ][1]);
                a[mi][1] = packh2(c_[mi][2*j  ][2], c_[mi][2*j  ][3]);
                a[mi][2] = packh2(c_[mi][2*j+1][0], c_[mi][2*j+1][1]);
                a[mi][3] = packh2(c_[mi][2*j+1][2], c_[mi][2*j+1][3]);
            }
            #pragma unroll
            for (int ni = 0; ni < 8; ++ni){
                int n = ni*8 + (lane>>2);
                unsigned b0 = Vb[n*20 + 8*j + (lane&3)];
                unsigned b1 = Vb[n*20 + 8*j + (lane&3) + 4];
                mma16f16(o[0][ni], a[0], b0, b1);
                mma16f16(o[1][ni], a[1], b0, b1);
            }
        }
        __syncthreads();
    }

    float* Og = op + base + (long)q0*(BSZ*EMB);
    #pragma unroll
    for (int mi = 0; mi < 2; ++mi){
        float inv0 = 1.f/l_[mi][0], inv1 = 1.f/l_[mi][1];
        int m = w*32 + mi*16 + (lane>>2);
        #pragma unroll
        for (int ni = 0; ni < 8; ++ni){
            int d = ni*8 + 2*(lane&3);
            *(float2*)(Og + (long)m    *(BSZ*EMB) + d) = make_float2(o[mi][ni][0]*inv0, o[mi][ni][1]*inv0);
            *(float2*)(Og + (long)(m+8)*(BSZ*EMB) + d) = make_float2(o[mi][ni][2]*inv1, o[mi][ni][3]*inv1);
        }
        if ((lane & 3) == 0){
            gm[(long)hb*S_LEN + q0 + m]     = m_[mi][0];
            gm[(long)hb*S_LEN + q0 + m + 8] = m_[mi][1];
            gl[(long)hb*S_LEN + q0 + m]     = l_[mi][0];
            gl[(long)hb*S_LEN + q0 + m + 8] = l_[mi][1];
        }
    }
}

// ---------------------------------------------------------------------------
// attn_avg (round-10 proven): 256 thr, k-tile 64, q-tile 128, double-buffered
// heads, tf32-bit LDS.64 frags, exp2-folded softmax.
// ---------------------------------------------------------------------------
__global__ __launch_bounds__(256)
void avg_attn(const float* __restrict__ qp, const float* __restrict__ kp,
              const float* __restrict__ gm, const float* __restrict__ gl,
              float* __restrict__ avg)
{
    extern __shared__ __align__(16) unsigned ASH[];
    constexpr int BUF = 128*72 + 64*72;
    const int tid = threadIdx.x, lane = tid&31, wid = tid>>5;
    const int k0 = blockIdx.x*64, q0 = blockIdx.y*128, b = blockIdx.z;
    const int rloc = wid*16 + (lane>>2);

    auto stage = [&](int h, int sel){
        unsigned* Qs = ASH + sel*BUF;
        unsigned* Ks = Qs + 128*72;
        const long base = (long)b*EMB + h*DH;
        #pragma unroll
        for (int j = 0; j < 8; ++j){
            int idx = tid + j*256;
            int r = idx>>4, c = (idx&15)*4;
            cpa16(&Qs[r*72 + c], qp + base + (long)(q0+r)*(BSZ*EMB) + c);
        }
        #pragma unroll
        for (int j = 0; j < 4; ++j){
            int idx = tid + j*256;
            int r = idx>>4, c = (idx&15)*4;
            cpa16(&Ks[r*72 + c], kp + base + (long)(k0+r)*(BSZ*EMB) + c);
        }
        asm volatile("cp.async.commit_group;\n");
    };

    float acc[8][4] = {};

    stage(0, 0);
    for (int h = 0; h < NH; ++h){
        if (h < NH-1){
            stage(h+1, (h+1)&1);
            asm volatile("cp.async.wait_group 1;\n");
        } else {
            asm volatile("cp.async.wait_group 0;\n");
        }
        __syncthreads();

        unsigned* Qs = ASH + (h&1)*BUF;
        unsigned* Ks = Qs + 128*72;

        float c_[8][4] = {};
        #pragma unroll
        for (int ks = 0; ks < 8; ++ks){
            int col = ks*8 + 2*(lane&3);
            uint2 u0 = *(const uint2*)&Qs[ rloc   *72 + col];
            uint2 u1 = *(const uint2*)&Qs[(rloc+8)*72 + col];
            unsigned a[4] = { u0.x, u1.x, u0.y, u1.y };
            #pragma unroll
            for (int ni = 0; ni < 8; ++ni){
                int n = ni*8 + (lane>>2);
                uint2 ub = *(const uint2*)&Ks[n*72 + col];
                unsigned bf[2] = { ub.x, ub.y };
                mma8(c_[ni], a, bf);
            }
        }

        const int hb = b*NH + h;
        float e0 = gm[(long)hb*S_LEN + q0 + rloc    ]*LOG2E
                 + __log2f(gl[(long)hb*S_LEN + q0 + rloc    ]) + 4.0f;
        float e1 = gm[(long)hb*S_LEN + q0 + rloc + 8]*LOG2E
                 + __log2f(gl[(long)hb*S_LEN + q0 + rloc + 8]) + 4.0f;
        #pragma unroll
        for (int ni = 0; ni < 8; ++ni){
            acc[ni][0] += exp2f(fmaf(c_[ni][0], LOG2E, -e0));
            acc[ni][1] += exp2f(fmaf(c_[ni][1], LOG2E, -e0));
            acc[ni][2] += exp2f(fmaf(c_[ni][2], LOG2E, -e1));
            acc[ni][3] += exp2f(fmaf(c_[ni][3], LOG2E, -e1));
        }
        __syncthreads();
    }

    float* out = avg + (long)b*S2;
    #pragma unroll
    for (int ni = 0; ni < 8; ++ni){
        int kc = k0 + ni*8 + 2*(lane&3);
        *(float2*)(out + (long)(q0+rloc)  *S_LEN + kc) = make_float2(acc[ni][0], acc[ni][1]);
        *(float2*)(out + (long)(q0+rloc+8)*S_LEN + kc) = make_float2(acc[ni][2], acc[ni][3]);
    }
}

// ---------------------------------------------------------------------------
extern "C" void kernel_launch(void* const* d_in, const int* in_sizes, int n_in,
                              void* d_out, int out_size)
{
    const float* query = (const float*)d_in[0];
    const float* key   = (const float*)d_in[1];
    const float* value = (const float*)d_in[2];
    const float* q_w = (const float*)d_in[3];
    const float* q_b = (const float*)d_in[4];
    const float* k_w = (const float*)d_in[5];
    const float* k_b = (const float*)d_in[6];
    const float* v_w = (const float*)d_in[7];
    const float* v_b = (const float*)d_in[8];
    const float* out_w = (const float*)d_in[9];
    const float* out_b = (const float*)d_in[10];

    float *qp, *kp, *vp, *op, *gm, *gl;
    __half* vh;
    cudaGetSymbolAddress((void**)&qp, g_Qp);
    cudaGetSymbolAddress((void**)&kp, g_Kp);
    cudaGetSymbolAddress((void**)&vp, g_Vp);
    cudaGetSymbolAddress((void**)&vh, g_Vh);
    cudaGetSymbolAddress((void**)&op, g_O);
    cudaGetSymbolAddress((void**)&gm, g_m);
    cudaGetSymbolAddress((void**)&gl, g_l);

    float* Z = (float*)d_out;                          // [S,B,E]
    float* attn_avg = (float*)d_out + (long)MROWS*EMB; // [B,S,S]

    // one-time stream/event setup (first call = eager correctness run)
    static cudaStream_t s2 = nullptr;
    static cudaEvent_t evFork = nullptr, evJoin = nullptr;
    if (!s2){
        cudaStreamCreateWithFlags(&s2, cudaStreamNonBlocking);
        cudaEventCreateWithFlags(&evFork, cudaEventDisableTiming);
        cudaEventCreateWithFlags(&evJoin, cudaEventDisableTiming);
        cudaFuncSetAttribute(avg_attn, cudaFuncAttributeMaxDynamicSharedMemorySize, 110592);
    }

    // 1) Q/K/V projections merged (Q,K -> permuted tf32 bits; V fp32)
    dim3 gqkv(EMB/128, MROWS/64, 3);
    qkv_proj<<<gqkv, 256>>>(query, key, value, q_w, q_b, k_w, k_b, v_w, v_b, qp, kp, vp);

    // 1b) V -> fp16 transposed layout for flash PV
    dim3 gvt(S_LEN/64, NHEADS, 1);
    v_transpose<<<gvt, 256>>>(vp, (unsigned*)vh);

    // 2) Flash attention (tf32 QK^T, fp16 PV)
    dim3 gfa(NHEADS, S_LEN/128, 1);
    flash_attn<<<gfa, 128>>>(qp, kp, vh, op, gm, gl);

    // fork: out_proj on s2 concurrent with avg_attn on main stream
    cudaEventRecord(evFork, 0);
    cudaStreamWaitEvent(s2, evFork, 0);

    dim3 gop(EMB/128, MROWS/64, 1);
    out_proj<<<gop, 256, 0, s2>>>(op, out_w, out_b, Z);
    cudaEventRecord(evJoin, s2);

    dim3 gav(S_LEN/64, S_LEN/128, BSZ);
    avg_attn<<<gav, 256, 110592>>>(qp, kp, gm, gl, attn_avg);

    // join
    cudaStreamWaitEvent(0, evJoin, 0);
}